// round 2
// baseline (speedup 1.0000x reference)
#include <cuda_runtime.h>
#include <math.h>

// Problem constants
#define B_HALF 4096
#define D_DIM  256
#define N_TOT  8192

// Tiling
#define TM 64          // rows per block
#define TN 128         // cols per j-tile
#define KC 64          // k chunk
#define NJT (N_TOT / TN)   // 64 j-tiles
#define NKC (D_DIM / KC)   // 4 k-chunks
#define NBLK (N_TOT / TM)  // 128 blocks
#define AS_STRIDE 65       // odd stride -> conflict-free transposed stores/reads
#define BS_STRIDE 129

// Scratch (no allocations allowed in kernel_launch)
__device__ float g_zn[(size_t)N_TOT * D_DIM];   // normalized rows, pre-scaled by sqrt(1/T)
__device__ float g_partial[NBLK];

// ---------------------------------------------------------------------------
// Kernel 1: L2-normalize each row, fold in sqrt(1/temperature) = sqrt(2).
// One block (256 threads) per row; D_DIM == 256 so thread t owns element t.
// ---------------------------------------------------------------------------
__global__ void norm_kernel(const float* __restrict__ zi, const float* __restrict__ zj) {
    int row = blockIdx.x;
    const float* src = (row < B_HALF) ? (zi + (size_t)row * D_DIM)
                                      : (zj + (size_t)(row - B_HALF) * D_DIM);
    int t = threadIdx.x;
    float v = src[t];
    float s = v * v;
    #pragma unroll
    for (int o = 16; o > 0; o >>= 1) s += __shfl_xor_sync(0xffffffffu, s, o);
    __shared__ float ws[8];
    if ((t & 31) == 0) ws[t >> 5] = s;
    __syncthreads();
    float tot = 0.f;
    #pragma unroll
    for (int w = 0; w < 8; w++) tot += ws[w];
    // scale = sqrt(2) / max(||z||, eps)  ->  dot of scaled rows == sim / T
    float scale = 1.41421356237309515f / fmaxf(sqrtf(tot), 1e-8f);
    g_zn[(size_t)row * D_DIM + t] = v * scale;
}

// ---------------------------------------------------------------------------
// Kernel 2: fused logits-GEMM + online sumexp + positive extraction.
// Block: 256 threads as (tx 0..15, ty 0..15). Micro-tile per thread:
//   rows  m = ty + 16u (u=0..3), cols n = tx + 16v (v=0..7)
// (strided mapping -> all inner-loop LDS are conflict-free or broadcast).
// Per j-tile: accumulate 4x8 fp32 dots over 4 K-chunks, then epilogue:
// sumexp (diagonal skipped) and positive logit (j == i +/- B_HALF).
// Fully deterministic: fixed-order reductions, no atomics.
// ---------------------------------------------------------------------------
__global__ void __launch_bounds__(256, 1) ntxent_kernel() {
    extern __shared__ float sm[];
    float* As = sm;                                 // [D_DIM][AS_STRIDE] (k-major, transposed)
    float* Bs = sm + D_DIM * AS_STRIDE;             // [KC][BS_STRIDE]

    const int tid = threadIdx.x;
    const int tx = tid & 15;
    const int ty = tid >> 4;
    const int rb = blockIdx.x * TM;

    // Load A tile (TM rows x full K) transposed into As[k][m]. float4 global reads.
    {
        const float4* src = reinterpret_cast<const float4*>(g_zn + (size_t)rb * D_DIM);
        #pragma unroll
        for (int i = 0; i < 16; i++) {
            int flat = i * 256 + tid;      // 4096 float4 = 64 rows x 64 f4
            int m  = flat >> 6;
            int k4 = flat & 63;
            float4 v = src[(size_t)m * 64 + k4];
            int k = k4 * 4;
            As[(k + 0) * AS_STRIDE + m] = v.x;
            As[(k + 1) * AS_STRIDE + m] = v.y;
            As[(k + 2) * AS_STRIDE + m] = v.z;
            As[(k + 3) * AS_STRIDE + m] = v.w;
        }
    }

    float sumexp[4] = {0.f, 0.f, 0.f, 0.f};
    float pos[4]    = {0.f, 0.f, 0.f, 0.f};

    const float4* gsrc = reinterpret_cast<const float4*>(g_zn);

    for (int jt = 0; jt < NJT; jt++) {
        const int jb = jt * TN;
        float acc[4][8];
        #pragma unroll
        for (int u = 0; u < 4; u++)
            #pragma unroll
            for (int v = 0; v < 8; v++) acc[u][v] = 0.f;

        for (int kc = 0; kc < NKC; kc++) {
            __syncthreads();   // previous chunk's consumers done (also orders A stores, 1st iter)
            // Load B chunk: rows jb..jb+127, k in [kc*KC, kc*KC+KC) -> Bs[k][j]
            #pragma unroll
            for (int i = 0; i < 8; i++) {
                int flat = i * 256 + tid;  // 2048 float4 = 128 rows x 16 f4
                int j  = flat >> 4;
                int k4 = flat & 15;
                float4 v = gsrc[(size_t)(jb + j) * 64 + kc * 16 + k4];
                int k = k4 * 4;
                Bs[(k + 0) * BS_STRIDE + j] = v.x;
                Bs[(k + 1) * BS_STRIDE + j] = v.y;
                Bs[(k + 2) * BS_STRIDE + j] = v.z;
                Bs[(k + 3) * BS_STRIDE + j] = v.w;
            }
            __syncthreads();

            const float* Ap = As + kc * KC * AS_STRIDE;
            #pragma unroll 4
            for (int k = 0; k < KC; k++) {
                float a[4], b[8];
                #pragma unroll
                for (int u = 0; u < 4; u++) a[u] = Ap[k * AS_STRIDE + ty + 16 * u];
                #pragma unroll
                for (int v = 0; v < 8; v++) b[v] = Bs[k * BS_STRIDE + tx + 16 * v];
                #pragma unroll
                for (int u = 0; u < 4; u++)
                    #pragma unroll
                    for (int v = 0; v < 8; v++)
                        acc[u][v] = fmaf(a[u], b[v], acc[u][v]);
            }
        }

        // Epilogue for this j-tile: masked sumexp + positive pick.
        #pragma unroll
        for (int u = 0; u < 4; u++) {
            int i = rb + ty + 16 * u;
            #pragma unroll
            for (int v = 0; v < 8; v++) {
                int j = jb + tx + 16 * v;
                float l = acc[u][v];
                float e = __expf(l);
                if (j != i) sumexp[u] += e;                          // diagonal masked
                if (j == i + B_HALF || j == i - B_HALF) pos[u] += l; // exactly one hit/row
            }
        }
    }

    // Reduce over the 16 tx-threads sharing each row (xor 1,2,4,8 stays in 16-lane half).
    #pragma unroll
    for (int o = 1; o < 16; o <<= 1) {
        #pragma unroll
        for (int u = 0; u < 4; u++) {
            sumexp[u] += __shfl_xor_sync(0xffffffffu, sumexp[u], o);
            pos[u]    += __shfl_xor_sync(0xffffffffu, pos[u],    o);
        }
    }

    __shared__ float contribS[16];
    if (tx == 0) {
        float c = 0.f;
        #pragma unroll
        for (int u = 0; u < 4; u++) c += logf(sumexp[u]) - pos[u];
        contribS[ty] = c;
    }
    __syncthreads();
    if (tid == 0) {
        float tot = 0.f;
        #pragma unroll
        for (int y = 0; y < 16; y++) tot += contribS[y];
        g_partial[blockIdx.x] = tot;
    }
}

// ---------------------------------------------------------------------------
// Kernel 3: sum 128 block partials, write mean. Deterministic.
// ---------------------------------------------------------------------------
__global__ void finish_kernel(float* __restrict__ out) {
    int t = threadIdx.x;   // 128 threads
    float s = g_partial[t];
    #pragma unroll
    for (int o = 16; o > 0; o >>= 1) s += __shfl_xor_sync(0xffffffffu, s, o);
    __shared__ float ws[4];
    if ((t & 31) == 0) ws[t >> 5] = s;
    __syncthreads();
    if (t == 0) out[0] = (ws[0] + ws[1] + ws[2] + ws[3]) * (1.0f / (float)N_TOT);
}

// ---------------------------------------------------------------------------
extern "C" void kernel_launch(void* const* d_in, const int* in_sizes, int n_in,
                              void* d_out, int out_size) {
    const float* zi = (const float*)d_in[0];
    const float* zj = (const float*)d_in[1];
    float* out = (float*)d_out;

    const size_t smem_bytes = (size_t)(D_DIM * AS_STRIDE + KC * BS_STRIDE) * sizeof(float); // ~97.3 KB
    cudaFuncSetAttribute(ntxent_kernel, cudaFuncAttributeMaxDynamicSharedMemorySize,
                         (int)smem_bytes);

    norm_kernel<<<N_TOT, 256>>>(zi, zj);
    ntxent_kernel<<<NBLK, 256, smem_bytes>>>();
    finish_kernel<<<1, 128>>>(out);
}

// round 4
// speedup vs baseline: 8.6063x; 8.6063x over previous
#include <cuda_runtime.h>
#include <cuda_bf16.h>
#include <cstdint>
#include <math.h>

#define N_TOT   8192
#define B_HALF  4096
#define D_DIM   256
#define TM      128
#define TN      128
#define NCHUNK  32          // 4096 cols / 128 per chunk (per j-half)
#define GRID_X  128         // 64 m-tiles x 2 halves

#define KS_B    528         // smem row stride in bytes (33*16 -> conflict-free ldmatrix)
#define TILE_B  (128 * KS_B)   // 67584 bytes per 128-row tile
#define SMEM_TOTAL (3 * TILE_B)   // A + 2x B = 202752

// Scratch (__device__ globals: no allocations allowed)
__device__ __nv_bfloat16 g_znb[(size_t)N_TOT * D_DIM];  // normalized rows * sqrt(2)
__device__ float g_se[2][N_TOT];
__device__ float g_pos[N_TOT];

// ---------------------------------------------------------------------------
__device__ __forceinline__ uint32_t smem_u32(const void* p) {
    uint32_t a;
    asm("{ .reg .u64 t; cvta.to.shared.u64 t, %1; cvt.u32.u64 %0, t; }" : "=r"(a) : "l"(p));
    return a;
}
#define CP_ASYNC16(dst, src) \
    asm volatile("cp.async.cg.shared.global [%0], [%1], 16;" :: "r"(dst), "l"(src))
#define CP_COMMIT() asm volatile("cp.async.commit_group;" ::: "memory")
#define CP_WAIT0()  asm volatile("cp.async.wait_group 0;" ::: "memory")

#define LDSM4(r, addr) \
    asm volatile("ldmatrix.sync.aligned.m8n8.x4.shared.b16 {%0,%1,%2,%3}, [%4];" \
        : "=r"((r)[0]), "=r"((r)[1]), "=r"((r)[2]), "=r"((r)[3]) : "r"(addr))

#define MMA16816(c, a, b0, b1) \
    asm volatile("mma.sync.aligned.m16n8k16.row.col.f32.bf16.bf16.f32 " \
        "{%0,%1,%2,%3}, {%4,%5,%6,%7}, {%8,%9}, {%0,%1,%2,%3};" \
        : "+f"((c)[0]), "+f"((c)[1]), "+f"((c)[2]), "+f"((c)[3]) \
        : "r"((a)[0]), "r"((a)[1]), "r"((a)[2]), "r"((a)[3]), "r"(b0), "r"(b1))

// ---------------------------------------------------------------------------
// Kernel 1: L2-normalize rows, fold sqrt(1/T)=sqrt(2), emit bf16.
// One warp per row (8 rows / 256-thread block).
// ---------------------------------------------------------------------------
__global__ void norm_kernel(const float* __restrict__ zi, const float* __restrict__ zj) {
    int row  = blockIdx.x * 8 + (threadIdx.x >> 5);
    int lane = threadIdx.x & 31;
    const float4* src = (row < B_HALF)
        ? (const float4*)(zi + (size_t)row * D_DIM)
        : (const float4*)(zj + (size_t)(row - B_HALF) * D_DIM);
    float4 a = src[lane];
    float4 b = src[lane + 32];
    float s = a.x * a.x + a.y * a.y + a.z * a.z + a.w * a.w
            + b.x * b.x + b.y * b.y + b.z * b.z + b.w * b.w;
    #pragma unroll
    for (int o = 16; o > 0; o >>= 1) s += __shfl_xor_sync(0xffffffffu, s, o);
    float scale = 1.41421356237309515f / fmaxf(sqrtf(s), 1e-8f);

    __nv_bfloat16* dst = g_znb + (size_t)row * D_DIM;
    __nv_bfloat162 p0 = __floats2bfloat162_rn(a.x * scale, a.y * scale);
    __nv_bfloat162 p1 = __floats2bfloat162_rn(a.z * scale, a.w * scale);
    __nv_bfloat162 p2 = __floats2bfloat162_rn(b.x * scale, b.y * scale);
    __nv_bfloat162 p3 = __floats2bfloat162_rn(b.z * scale, b.w * scale);
    uint2 u0, u1;
    u0.x = *(uint32_t*)&p0; u0.y = *(uint32_t*)&p1;
    u1.x = *(uint32_t*)&p2; u1.y = *(uint32_t*)&p3;
    *(uint2*)(dst + lane * 4)       = u0;
    *(uint2*)(dst + 128 + lane * 4) = u1;
}

// ---------------------------------------------------------------------------
// Kernel 2: mma.sync bf16 GEMM fused with masked sumexp + positive pick.
// CTA (mtile, h): rows [mtile*128,+128) x cols [h*4096,+4096) in 32 chunks.
// 8 warps as 2(m) x 4(n); warp tile 64x32; frag m16n8k16.
// ---------------------------------------------------------------------------
__global__ void __launch_bounds__(256, 1) ntxent_kernel() {
    extern __shared__ char smem[];
    __shared__ float red[4][128];

    const int tid = threadIdx.x, lane = tid & 31, w = tid >> 5;
    const int wm = w >> 2, wn = w & 3;
    const int warpM0 = wm * 64, warpN0 = wn * 32;
    const int g = lane >> 2, tig = lane & 3;

    const int mtile = blockIdx.x & 63, h = blockIdx.x >> 6;
    const int m0 = mtile * TM;
    const int jbase = h * B_HALF;
    const int spec_chunk = (m0 & (B_HALF - 1)) >> 7;
    const bool diag_cta = ((m0 >> 12) == h);

    const uint32_t sbase = smem_u32(smem);
    const uint32_t sA = sbase;
    const uint32_t sBb = sbase + TILE_B;

    // ---- prologue: async-load A tile and B chunk 0 ----
    {
        const char* gA = (const char*)(g_znb + (size_t)m0 * D_DIM);
        #pragma unroll
        for (int it = 0; it < 16; it++) {
            int flat = it * 256 + tid;
            int r = flat >> 5, q = flat & 31;
            CP_ASYNC16(sA + r * KS_B + q * 16, gA + r * 512 + q * 16);
        }
        const char* gB = (const char*)(g_znb + (size_t)jbase * D_DIM);
        #pragma unroll
        for (int it = 0; it < 16; it++) {
            int flat = it * 256 + tid;
            int r = flat >> 5, q = flat & 31;
            CP_ASYNC16(sBb + r * KS_B + q * 16, gB + r * 512 + q * 16);
        }
    }
    CP_COMMIT();
    CP_WAIT0();
    __syncthreads();

    float rowsum[8];
    #pragma unroll
    for (int s = 0; s < 8; s++) rowsum[s] = 0.f;

    for (int c = 0; c < NCHUNK; c++) {
        // ---- issue next B chunk into the other buffer ----
        if (c + 1 < NCHUNK) {
            const uint32_t sBn = sBb + ((c + 1) & 1) * TILE_B;
            const char* gB = (const char*)(g_znb + (size_t)(jbase + (c + 1) * TN) * D_DIM);
            #pragma unroll
            for (int it = 0; it < 16; it++) {
                int flat = it * 256 + tid;
                int r = flat >> 5, q = flat & 31;
                CP_ASYNC16(sBn + r * KS_B + q * 16, gB + r * 512 + q * 16);
            }
        }
        CP_COMMIT();

        // ---- compute 128x128 chunk ----
        const uint32_t sB = sBb + (c & 1) * TILE_B;
        float acc[4][4][4];
        #pragma unroll
        for (int mf = 0; mf < 4; mf++)
            #pragma unroll
            for (int nf = 0; nf < 4; nf++)
                #pragma unroll
                for (int e = 0; e < 4; e++) acc[mf][nf][e] = 0.f;

        #pragma unroll 4
        for (int kk = 0; kk < 16; kk++) {
            const int kb = kk * 32;                 // byte offset of k16 step
            uint32_t af[4][4], bf[2][4];
            #pragma unroll
            for (int mf = 0; mf < 4; mf++) {
                uint32_t addr = sA + (warpM0 + mf * 16 + (lane & 15)) * KS_B
                              + kb + ((lane >> 4) & 1) * 16;
                LDSM4(af[mf], addr);
            }
            #pragma unroll
            for (int p = 0; p < 2; p++) {
                uint32_t addr = sB + (warpN0 + p * 16 + ((lane & 16) >> 1) + (lane & 7)) * KS_B
                              + kb + ((lane >> 3) & 1) * 16;
                LDSM4(bf[p], addr);
            }
            #pragma unroll
            for (int mf = 0; mf < 4; mf++)
                #pragma unroll
                for (int nf = 0; nf < 4; nf++)
                    MMA16816(acc[mf][nf], af[mf], bf[nf >> 1][(nf & 1) * 2],
                             bf[nf >> 1][(nf & 1) * 2 + 1]);
        }

        // ---- fused epilogue: exp + row sums; diagonal/positive in spec chunk ----
        if (c == spec_chunk) {
            #pragma unroll
            for (int mf = 0; mf < 4; mf++)
                #pragma unroll
                for (int nf = 0; nf < 4; nf++)
                    #pragma unroll
                    for (int e = 0; e < 4; e++) {
                        float l = acc[mf][nf][e];
                        float ex = __expf(l);
                        int lr = warpM0 + mf * 16 + g + (e >> 1) * 8;
                        int lc = warpN0 + nf * 8 + tig * 2 + (e & 1);
                        if (lr == lc) {
                            if (diag_cta) ex = 0.f;            // self-similarity
                            else          g_pos[m0 + lr] = l;  // positive logit
                        }
                        rowsum[mf * 2 + (e >> 1)] += ex;
                    }
        } else {
            #pragma unroll
            for (int mf = 0; mf < 4; mf++)
                #pragma unroll
                for (int nf = 0; nf < 4; nf++)
                    #pragma unroll
                    for (int e = 0; e < 4; e++)
                        rowsum[mf * 2 + (e >> 1)] += __expf(acc[mf][nf][e]);
        }

        CP_WAIT0();
        __syncthreads();
    }

    // ---- reduce across the 4 lanes sharing each row ----
    #pragma unroll
    for (int s = 0; s < 8; s++) {
        rowsum[s] += __shfl_xor_sync(0xffffffffu, rowsum[s], 1);
        rowsum[s] += __shfl_xor_sync(0xffffffffu, rowsum[s], 2);
    }
    if (tig == 0) {
        #pragma unroll
        for (int mf = 0; mf < 4; mf++) {
            red[wn][warpM0 + mf * 16 + g]     = rowsum[mf * 2 + 0];
            red[wn][warpM0 + mf * 16 + g + 8] = rowsum[mf * 2 + 1];
        }
    }
    __syncthreads();
    if (tid < 128) {
        g_se[h][m0 + tid] = (red[0][tid] + red[1][tid]) + (red[2][tid] + red[3][tid]);
    }
}

// ---------------------------------------------------------------------------
// Kernel 3: loss = mean_i( log(se0[i]+se1[i]) - pos[i] ). Deterministic.
// ---------------------------------------------------------------------------
__global__ void finish_kernel(float* __restrict__ out) {
    __shared__ float ws[8];
    int t = threadIdx.x;   // 256 threads
    float s = 0.f;
    #pragma unroll
    for (int k = 0; k < 32; k++) {
        int i = t + k * 256;
        s += logf(g_se[0][i] + g_se[1][i]) - g_pos[i];
    }
    #pragma unroll
    for (int o = 16; o > 0; o >>= 1) s += __shfl_xor_sync(0xffffffffu, s, o);
    if ((t & 31) == 0) ws[t >> 5] = s;
    __syncthreads();
    if (t == 0) {
        float tot = 0.f;
        #pragma unroll
        for (int x = 0; x < 8; x++) tot += ws[x];
        out[0] = tot * (1.0f / (float)N_TOT);
    }
}

// ---------------------------------------------------------------------------
extern "C" void kernel_launch(void* const* d_in, const int* in_sizes, int n_in,
                              void* d_out, int out_size) {
    const float* zi = (const float*)d_in[0];
    const float* zj = (const float*)d_in[1];
    float* out = (float*)d_out;

    cudaFuncSetAttribute(ntxent_kernel, cudaFuncAttributeMaxDynamicSharedMemorySize,
                         SMEM_TOTAL);

    norm_kernel<<<N_TOT / 8, 256>>>(zi, zj);
    ntxent_kernel<<<GRID_X, 256, SMEM_TOTAL>>>();
    finish_kernel<<<1, 256>>>(out);
}

// round 5
// speedup vs baseline: 14.2982x; 1.6614x over previous
#include <cuda_runtime.h>
#include <cuda_bf16.h>
#include <cstdint>
#include <math.h>

#define N_TOT    8192
#define B_HALF   4096
#define D_DIM    256
#define NBLOCKS  64          // 8192 / 128 row/col blocks
#define NTILE    2080        // 64*65/2 upper-triangle tiles
#define GRID_MAIN 148

#define KS_B    528          // smem row stride bytes (33*16, conflict-free ldmatrix)
#define TILE_B  (128 * KS_B) // 67584 per 128-row tile
#define SMEM_TOTAL (3 * TILE_B)   // A + 2x B

// Scratch (__device__ globals; every slot read is rewritten each run)
__device__ __nv_bfloat16 g_znb[(size_t)N_TOT * D_DIM];
__device__ float g_rowpart[NBLOCKS][NBLOCKS][128];   // [mt][nt] valid for nt>=mt
__device__ float g_colpart[NBLOCKS][NBLOCKS][128];   // [nt][mt] valid for mt<nt
__device__ float g_pos[N_TOT];
__device__ float g_finpart[NBLOCKS];

// ---------------------------------------------------------------------------
__device__ __forceinline__ uint32_t smem_u32(const void* p) {
    uint32_t a;
    asm("{ .reg .u64 t; cvta.to.shared.u64 t, %1; cvt.u32.u64 %0, t; }" : "=r"(a) : "l"(p));
    return a;
}
#define CP_ASYNC16(dst, src) \
    asm volatile("cp.async.cg.shared.global [%0], [%1], 16;" :: "r"(dst), "l"(src))
#define CP_COMMIT() asm volatile("cp.async.commit_group;" ::: "memory")
#define CP_WAIT0()  asm volatile("cp.async.wait_group 0;" ::: "memory")

#define LDSM4(r, addr) \
    asm volatile("ldmatrix.sync.aligned.m8n8.x4.shared.b16 {%0,%1,%2,%3}, [%4];" \
        : "=r"((r)[0]), "=r"((r)[1]), "=r"((r)[2]), "=r"((r)[3]) : "r"(addr))

#define MMA16816(c, a, b0, b1) \
    asm volatile("mma.sync.aligned.m16n8k16.row.col.f32.bf16.bf16.f32 " \
        "{%0,%1,%2,%3}, {%4,%5,%6,%7}, {%8,%9}, {%0,%1,%2,%3};" \
        : "+f"((c)[0]), "+f"((c)[1]), "+f"((c)[2]), "+f"((c)[3]) \
        : "r"((a)[0]), "r"((a)[1]), "r"((a)[2]), "r"((a)[3]), "r"(b0), "r"(b1))

// ---------------------------------------------------------------------------
// Kernel 1: L2-normalize rows, fold sqrt(1/T)=sqrt(2), emit bf16.
// ---------------------------------------------------------------------------
__global__ void norm_kernel(const float* __restrict__ zi, const float* __restrict__ zj) {
    int row  = blockIdx.x * 8 + (threadIdx.x >> 5);
    int lane = threadIdx.x & 31;
    const float4* src = (row < B_HALF)
        ? (const float4*)(zi + (size_t)row * D_DIM)
        : (const float4*)(zj + (size_t)(row - B_HALF) * D_DIM);
    float4 a = src[lane];
    float4 b = src[lane + 32];
    float s = a.x * a.x + a.y * a.y + a.z * a.z + a.w * a.w
            + b.x * b.x + b.y * b.y + b.z * b.z + b.w * b.w;
    #pragma unroll
    for (int o = 16; o > 0; o >>= 1) s += __shfl_xor_sync(0xffffffffu, s, o);
    float scale = 1.41421356237309515f / fmaxf(sqrtf(s), 1e-8f);

    __nv_bfloat16* dst = g_znb + (size_t)row * D_DIM;
    __nv_bfloat162 p0 = __floats2bfloat162_rn(a.x * scale, a.y * scale);
    __nv_bfloat162 p1 = __floats2bfloat162_rn(a.z * scale, a.w * scale);
    __nv_bfloat162 p2 = __floats2bfloat162_rn(b.x * scale, b.y * scale);
    __nv_bfloat162 p3 = __floats2bfloat162_rn(b.z * scale, b.w * scale);
    uint2 u0, u1;
    u0.x = *(uint32_t*)&p0; u0.y = *(uint32_t*)&p1;
    u1.x = *(uint32_t*)&p2; u1.y = *(uint32_t*)&p3;
    *(uint2*)(dst + lane * 4)       = u0;
    *(uint2*)(dst + 128 + lane * 4) = u1;
}

// ---------------------------------------------------------------------------
// Kernel 2: upper-triangle tiles only. Per off-diag tile: row-sums of exp ->
// block mt, col-sums of exp -> block nt (symmetry). Slot writes, no atomics.
// 148 persistent CTAs, contiguous tile ranges. A single-buffered (reload on
// mt change), B double-buffered via cp.async.
// ---------------------------------------------------------------------------
__global__ void __launch_bounds__(256, 1) ntxent_kernel() {
    extern __shared__ char smem[];
    __shared__ float red_r[4][128];
    __shared__ float red_c[2][128];

    const int tid = threadIdx.x, lane = tid & 31, w = tid >> 5;
    const int wm = w >> 2, wn = w & 3;
    const int warpM0 = wm * 64, warpN0 = wn * 32;
    const int g = lane >> 2, tig = lane & 3;

    const uint32_t sbase = smem_u32(smem);
    const uint32_t sA = sbase;
    const uint32_t sBb = sbase + TILE_B;

    const int t0 = (blockIdx.x * NTILE) / GRID_MAIN;
    const int t1 = ((blockIdx.x + 1) * NTILE) / GRID_MAIN;

    // coords of tile t0 in the packed upper triangle
    int mt = 0, rem = t0;
    while (rem >= NBLOCKS - mt) { rem -= NBLOCKS - mt; mt++; }
    int nt = mt + rem;

    // prologue: A(mt) and B(nt) into buf0
    {
        const char* gA = (const char*)(g_znb + (size_t)mt * 128 * D_DIM);
        const char* gB = (const char*)(g_znb + (size_t)nt * 128 * D_DIM);
        #pragma unroll
        for (int it = 0; it < 16; it++) {
            int flat = it * 256 + tid;
            int r = flat >> 5, q = flat & 31;
            CP_ASYNC16(sA + r * KS_B + q * 16, gA + r * 512 + q * 16);
            CP_ASYNC16(sBb + r * KS_B + q * 16, gB + r * 512 + q * 16);
        }
    }
    CP_COMMIT();
    CP_WAIT0();
    __syncthreads();

    int cur_mt = mt;
    for (int t = t0; t < t1; t++) {
        const int buf = (t - t0) & 1;
        const bool have_next = (t + 1 < t1);
        int nmt = mt, nnt = nt + 1;
        if (nnt == NBLOCKS) { nmt = mt + 1; nnt = nmt; }

        if (have_next) {   // prefetch next tile's B into the other buffer
            const uint32_t sBn = sBb + (buf ^ 1) * TILE_B;
            const char* gB = (const char*)(g_znb + (size_t)nnt * 128 * D_DIM);
            #pragma unroll
            for (int it = 0; it < 16; it++) {
                int flat = it * 256 + tid;
                int r = flat >> 5, q = flat & 31;
                CP_ASYNC16(sBn + r * KS_B + q * 16, gB + r * 512 + q * 16);
            }
        }
        CP_COMMIT();

        // ---- 128x128x256 tile GEMM ----
        const uint32_t sB = sBb + buf * TILE_B;
        float acc[4][4][4];
        #pragma unroll
        for (int mf = 0; mf < 4; mf++)
            #pragma unroll
            for (int nf = 0; nf < 4; nf++)
                #pragma unroll
                for (int e = 0; e < 4; e++) acc[mf][nf][e] = 0.f;

        #pragma unroll 4
        for (int kk = 0; kk < 16; kk++) {
            const int kb = kk * 32;
            uint32_t af[4][4], bf[2][4];
            #pragma unroll
            for (int mf = 0; mf < 4; mf++) {
                uint32_t addr = sA + (warpM0 + mf * 16 + (lane & 15)) * KS_B
                              + kb + ((lane >> 4) & 1) * 16;
                LDSM4(af[mf], addr);
            }
            #pragma unroll
            for (int p = 0; p < 2; p++) {
                uint32_t addr = sB + (warpN0 + p * 16 + ((lane & 16) >> 1) + (lane & 7)) * KS_B
                              + kb + ((lane >> 3) & 1) * 16;
                LDSM4(bf[p], addr);
            }
            #pragma unroll
            for (int mf = 0; mf < 4; mf++)
                #pragma unroll
                for (int nf = 0; nf < 4; nf++)
                    MMA16816(acc[mf][nf], af[mf], bf[nf >> 1][(nf & 1) * 2],
                             bf[nf >> 1][(nf & 1) * 2 + 1]);
        }

        // ---- epilogue: exp, row sums + col sums, diag/positive handling ----
        const bool is_diag = (mt == nt);
        const bool is_pos  = (nt == mt + 32);
        const int  m0 = mt * 128;

        float rowsum[8], colsum[8];
        #pragma unroll
        for (int s = 0; s < 8; s++) { rowsum[s] = 0.f; colsum[s] = 0.f; }

        #pragma unroll
        for (int mf = 0; mf < 4; mf++)
            #pragma unroll
            for (int nf = 0; nf < 4; nf++)
                #pragma unroll
                for (int e = 0; e < 4; e++) {
                    float l = acc[mf][nf][e];
                    float ex = __expf(l);
                    int lr = warpM0 + mf * 16 + g + (e >> 1) * 8;
                    int lc = warpN0 + nf * 8 + tig * 2 + (e & 1);
                    if (lr == lc) {
                        if (is_diag) ex = 0.f;            // self-similarity
                        if (is_pos) {                     // positive pair logit
                            g_pos[m0 + lr] = l;
                            g_pos[m0 + lr + B_HALF] = l;
                        }
                    }
                    rowsum[mf * 2 + (e >> 1)] += ex;
                    colsum[nf * 2 + (e & 1)]  += ex;
                }

        // row reduce over the 4 tig lanes
        #pragma unroll
        for (int s = 0; s < 8; s++) {
            rowsum[s] += __shfl_xor_sync(0xffffffffu, rowsum[s], 1);
            rowsum[s] += __shfl_xor_sync(0xffffffffu, rowsum[s], 2);
        }
        // col reduce over the 8 g lanes
        #pragma unroll
        for (int s = 0; s < 8; s++) {
            colsum[s] += __shfl_xor_sync(0xffffffffu, colsum[s], 4);
            colsum[s] += __shfl_xor_sync(0xffffffffu, colsum[s], 8);
            colsum[s] += __shfl_xor_sync(0xffffffffu, colsum[s], 16);
        }
        if (tig == 0) {
            #pragma unroll
            for (int mf = 0; mf < 4; mf++) {
                red_r[wn][warpM0 + mf * 16 + g]     = rowsum[mf * 2 + 0];
                red_r[wn][warpM0 + mf * 16 + g + 8] = rowsum[mf * 2 + 1];
            }
        }
        if (g == 0) {
            #pragma unroll
            for (int nf = 0; nf < 4; nf++) {
                red_c[wm][warpN0 + nf * 8 + tig * 2]     = colsum[nf * 2 + 0];
                red_c[wm][warpN0 + nf * 8 + tig * 2 + 1] = colsum[nf * 2 + 1];
            }
        }
        __syncthreads();
        if (tid < 128) {
            float rp = (red_r[0][tid] + red_r[1][tid]) + (red_r[2][tid] + red_r[3][tid]);
            g_rowpart[mt][nt][tid] = rp;
            if (!is_diag) g_colpart[nt][mt][tid] = red_c[0][tid] + red_c[1][tid];
        }

        CP_WAIT0();        // next B landed; also drains any stragglers
        __syncthreads();   // red_* and B buffer safe to reuse

        if (have_next && nmt != cur_mt) {   // A reload on row change
            const char* gA = (const char*)(g_znb + (size_t)nmt * 128 * D_DIM);
            #pragma unroll
            for (int it = 0; it < 16; it++) {
                int flat = it * 256 + tid;
                int r = flat >> 5, q = flat & 31;
                CP_ASYNC16(sA + r * KS_B + q * 16, gA + r * 512 + q * 16);
            }
            CP_COMMIT();
            CP_WAIT0();
            __syncthreads();
            cur_mt = nmt;
        }
        mt = nmt; nt = nnt;
    }
}

// ---------------------------------------------------------------------------
// Kernel 3a: per-row total = sum of 64 slot partials; contrib = log(total)-pos.
// 64 blocks x 128 threads (one thread per row). Deterministic.
// ---------------------------------------------------------------------------
__global__ void finishA_kernel() {
    __shared__ float ws[4];
    const int r = blockIdx.x, tid = threadIdx.x;
    float tot = 0.f;
    for (int nt = r; nt < NBLOCKS; nt++) tot += g_rowpart[r][nt][tid];
    for (int m = 0; m < r; m++)          tot += g_colpart[r][m][tid];
    float v = logf(tot) - g_pos[r * 128 + tid];
    #pragma unroll
    for (int o = 16; o > 0; o >>= 1) v += __shfl_xor_sync(0xffffffffu, v, o);
    if ((tid & 31) == 0) ws[tid >> 5] = v;
    __syncthreads();
    if (tid == 0) g_finpart[r] = (ws[0] + ws[1]) + (ws[2] + ws[3]);
}

// ---------------------------------------------------------------------------
// Kernel 3b: final mean.
// ---------------------------------------------------------------------------
__global__ void finishB_kernel(float* __restrict__ out) {
    __shared__ float ws[2];
    int t = threadIdx.x;   // 64 threads
    float s = g_finpart[t];
    #pragma unroll
    for (int o = 16; o > 0; o >>= 1) s += __shfl_xor_sync(0xffffffffu, s, o);
    if ((t & 31) == 0) ws[t >> 5] = s;
    __syncthreads();
    if (t == 0) out[0] = (ws[0] + ws[1]) * (1.0f / (float)N_TOT);
}

// ---------------------------------------------------------------------------
extern "C" void kernel_launch(void* const* d_in, const int* in_sizes, int n_in,
                              void* d_out, int out_size) {
    const float* zi = (const float*)d_in[0];
    const float* zj = (const float*)d_in[1];
    float* out = (float*)d_out;

    cudaFuncSetAttribute(ntxent_kernel, cudaFuncAttributeMaxDynamicSharedMemorySize,
                         SMEM_TOTAL);

    norm_kernel<<<N_TOT / 8, 256>>>(zi, zj);
    ntxent_kernel<<<GRID_MAIN, 256, SMEM_TOTAL>>>();
    finishA_kernel<<<NBLOCKS, 128>>>();
    finishB_kernel<<<1, 64>>>(out);
}